// round 6
// baseline (speedup 1.0000x reference)
#include <cuda_runtime.h>
#include <stdint.h>

// Problem constants (fixed shapes from reference): x = (32, 3, 512, 512) f32.
// 96 images, 8x8 tile grid, tiles of 64x64 (area 4096), 256 bins, clip=32.
#define N_IMG      96
#define IMG_H      512
#define IMG_W      512
#define IMG_PIX    (IMG_H * IMG_W)          // 262144
#define GRID_G     8
#define TILE_H     64
#define TILE_W     64
#define NBINS      256
#define CLIP_V     32
#define N_TILES    (N_IMG * GRID_G * GRID_G) // 6144
#define N_BANDS    (N_IMG * 32)              // 16-row bands
#define NSUB       8

// Scratch (all __device__ globals; no allocation anywhere).
__device__ uint8_t  g_img[(size_t)N_IMG * IMG_PIX];   // 24 MiB quantized image
__device__ uint8_t  g_lut[(size_t)N_TILES * NBINS];   // 1.5 MiB per-tile LUTs
__device__ int      g_img_done[N_IMG];                // tiles completed per image
__device__ unsigned g_band_next;                      // dynamic band queue head

// ---------------------------------------------------------------------------
__global__ void clahe_init_kernel()
{
    int t = threadIdx.x;
    if (t < N_IMG) g_img_done[t] = 0;
    if (t == 0)    g_band_next  = 0;
}

// ---------------------------------------------------------------------------
// Fused persistent kernel.
//   Blocks [0, P): producers — per-tile histogram -> clip -> redistribute ->
//     cdf -> LUT, quantizing the f32 image to u8 scratch on the way; each
//     completed tile increments its image's done-counter (release).
//   All blocks then pull 16-row apply-bands from a global atomic queue; a
//   band spin-waits (tid0 + nanosleep) until its image's 64 tiles are done.
// DEADLOCK SAFETY: the host sizes the grid to SMs * (occupancy-API resident
// blocks), so EVERY block is resident in wave 1; producers always progress.
// ---------------------------------------------------------------------------
__global__ void __launch_bounds__(256, 6)
clahe_fused_kernel(const float* __restrict__ x, float* __restrict__ out)
{
    __shared__ union {
        struct { int hist[NSUB * NBINS]; } a;                      // 8 KB
        struct { uint8_t lut[2][GRID_G * NBINS];                   // 4 KB
                 unsigned comb[9 * NBINS]; } b;                    // 9 KB
    } sm;
    __shared__ int s_excess;
    __shared__ int s_warp[8];
    __shared__ int s_band;

    const int tid  = threadIdx.x;
    const int bid  = blockIdx.x;
    const int NB   = gridDim.x;
    const int P    = NB >> 1;                 // producer blocks
    const int lane = tid & 31, wid = tid >> 5;

    // ============================ PRODUCE =================================
    if (bid < P) {
        for (int tile = bid; tile < N_TILES; tile += P) {
            const int bc = tile >> 6;
            const int t  = tile & 63;
            const int gy = t >> 3;
            const int gx = t & 7;

            #pragma unroll
            for (int i = 0; i < NSUB; i++) sm.a.hist[tid + i * 256] = 0;
            if (tid == 0) s_excess = 0;
            __syncthreads();

            const float* img  = x + (size_t)bc * IMG_PIX;
            uint8_t*     dimg = g_img + (size_t)bc * IMG_PIX;
            const int row0 = gy * TILE_H;
            const int col0 = gx * TILE_W;
            const int sub  = tid & (NSUB - 1);

            float4 v[4];
            size_t offs[4];
            #pragma unroll
            for (int i = 0; i < 4; i++) {
                int q  = tid + i * 256;       // float4 index within tile
                int r  = q >> 4;
                int c4 = q & 15;
                offs[i] = (size_t)(row0 + r) * IMG_W + col0 + c4 * 4;
                v[i]    = *(const float4*)(img + offs[i]);
            }
            #pragma unroll
            for (int i = 0; i < 4; i++) {
                // match jnp.round (round-half-even) of clip(x,0,1)*255
                unsigned p0 = (unsigned)rintf(__saturatef(v[i].x) * 255.0f);
                unsigned p1 = (unsigned)rintf(__saturatef(v[i].y) * 255.0f);
                unsigned p2 = (unsigned)rintf(__saturatef(v[i].z) * 255.0f);
                unsigned p3 = (unsigned)rintf(__saturatef(v[i].w) * 255.0f);
                atomicAdd(&sm.a.hist[p0 * NSUB + sub], 1);
                atomicAdd(&sm.a.hist[p1 * NSUB + sub], 1);
                atomicAdd(&sm.a.hist[p2 * NSUB + sub], 1);
                atomicAdd(&sm.a.hist[p3 * NSUB + sub], 1);
                unsigned packed = p0 | (p1 << 8) | (p2 << 16) | (p3 << 24);
                *(unsigned*)(dimg + offs[i]) = packed;
            }
            __syncthreads();

            // merge sub-histograms (8 contiguous ints per bin = 2 x int4)
            int4 ha = ((const int4*)sm.a.hist)[tid * 2 + 0];
            int4 hb = ((const int4*)sm.a.hist)[tid * 2 + 1];
            int h   = ha.x + ha.y + ha.z + ha.w + hb.x + hb.y + hb.z + hb.w;

            int clipped = min(h, CLIP_V);
            int over    = h - clipped;
            #pragma unroll
            for (int o = 16; o > 0; o >>= 1)
                over += __shfl_down_sync(0xffffffffu, over, o);
            if (lane == 0) atomicAdd(&s_excess, over);
            __syncthreads();

            const int excess    = s_excess;
            const int batch_add = excess >> 8;
            const int residual  = excess & 255;
            const int step      = max(256 / max(residual, 1), 1);
            const int extra     = ((tid % step) == 0 && (tid / step) < residual) ? 1 : 0;
            int vv = clipped + batch_add + extra;

            // inclusive scan over 256 bins
            int sv = vv;
            #pragma unroll
            for (int o = 1; o < 32; o <<= 1) {
                int n = __shfl_up_sync(0xffffffffu, sv, o);
                if (lane >= o) sv += n;
            }
            if (lane == 31) s_warp[wid] = sv;
            __syncthreads();
            if (wid == 0 && lane < 8) {
                int w = s_warp[lane];
                #pragma unroll
                for (int o = 1; o < 8; o <<= 1) {
                    int n = __shfl_up_sync(0x000000ffu, w, o);
                    if (lane >= o) w += n;
                }
                s_warp[lane] = w;
            }
            __syncthreads();
            int cdf = sv + (wid ? s_warp[wid - 1] : 0);   // 1..4096

            float lf = rintf((float)cdf * (255.0f / 4096.0f));
            int   li = min(max((int)lf, 0), 255);
            g_lut[(size_t)tile * NBINS + tid] = (uint8_t)li;

            // release: make tile's lut + img bytes visible, then count it
            __threadfence();
            __syncthreads();
            if (tid == 0) atomicAdd(&g_img_done[bc], 1);
        }
    }

    // ============================ CONSUME =================================
    while (true) {
        if (tid == 0) s_band = (int)atomicAdd(&g_band_next, 1u);
        __syncthreads();
        const int band = s_band;
        __syncthreads();
        if (band >= N_BANDS) break;

        const int bc = band >> 5;
        const int hb = band & 31;
        const int y0 = hb * 16;

        if (tid == 0) {
            while (atomicAdd(&g_img_done[bc], 0) < 64) __nanosleep(128);
        }
        __syncthreads();
        __threadfence();   // acquire side

        // tile-row pair for this 16-row band (constant within the band)
        const int i1u = (hb - 2) >> 2;
        const int ty1 = max(i1u, 0);
        const int ty2 = min(i1u + 1, GRID_G - 1);

        // stage the two LUT rows (2048 B each), L2-path loads
        {
            const uint4* lutA = (const uint4*)(g_lut + ((size_t)(bc * GRID_G + ty1) * GRID_G) * NBINS);
            const uint4* lutB = (const uint4*)(g_lut + ((size_t)(bc * GRID_G + ty2) * GRID_G) * NBINS);
            if (tid < 128) ((uint4*)sm.b.lut[0])[tid]       = __ldcg(&lutA[tid]);
            else           ((uint4*)sm.b.lut[1])[tid - 128] = __ldcg(&lutB[tid - 128]);
        }
        __syncthreads();

        // fused 4-way LUT: one u32 per (col-pair, bin)
        #pragma unroll
        for (int p = 0; p < 9; p++) {
            int tx1 = max(p - 1, 0);
            int tx2 = min(p, GRID_G - 1);
            unsigned l11 = sm.b.lut[0][tx1 * NBINS + tid];
            unsigned l12 = sm.b.lut[0][tx2 * NBINS + tid];
            unsigned l21 = sm.b.lut[1][tx1 * NBINS + tid];
            unsigned l22 = sm.b.lut[1][tx2 * NBINS + tid];
            sm.b.comb[p * NBINS + tid] = l11 | (l12 << 8) | (l21 << 16) | (l22 << 24);
        }
        __syncthreads();

        const uint8_t* dimg = g_img + (size_t)bc * IMG_PIX + (size_t)y0 * IMG_W;
        float*         o    = out   + (size_t)bc * IMG_PIX + (size_t)y0 * IMG_W;

        // per-thread x-position is loop-invariant (c4 = tid & 127)
        const int c4   = tid & 127;
        const int r0   = tid >> 7;
        const int x0   = c4 * 4;
        const int pair = (x0 + 32) >> 6;
        const int iax0 = (x0 + 32) & 63;
        const unsigned* comb = &sm.b.comb[pair * NBINS];

        unsigned wAv[4];
        #pragma unroll
        for (int j = 0; j < 4; j++) {
            int iax = iax0 + j;
            wAv[j] = (unsigned)(64 - iax) | ((unsigned)iax << 8);
        }

        #pragma unroll
        for (int it = 0; it < 8; it++) {
            int r    = r0 + it * 2;
            int iay  = (y0 + r + 32) & 63;
            int wy1i = 64 - iay;

            unsigned p = *(const unsigned*)(dimg + (size_t)r * IMG_W + x0);

            float4 res;
            float* rp = (float*)&res;
            #pragma unroll
            for (int j = 0; j < 4; j++) {
                unsigned L = comb[(p >> (8 * j)) & 255];
                int A = __dp4a(L, wAv[j], 0u);        // top-row horiz interp
                int B = __dp4a(L, wAv[j] << 16, 0u);  // bottom-row horiz interp
                int N = A * wy1i + B * iay;           // res * 4096, exact

                // round-half-even(N/4096): N < 2^20 so i2f & *2^-12 are exact
                float kf = rintf((float)N * 0x1p-12f);
                rp[j] = kf * (1.0f / 255.0f);         // <= 1 ulp vs exact div
            }
            *(float4*)(o + (size_t)r * IMG_W + x0) = res;
        }
        __syncthreads();   // protect sm.b before next band's staging
    }
}

// ---------------------------------------------------------------------------
extern "C" void kernel_launch(void* const* d_in, const int* in_sizes, int n_in,
                              void* d_out, int out_size)
{
    const float* x   = (const float*)d_in[0];
    float*       out = (float*)d_out;
    (void)in_sizes; (void)n_in; (void)out_size;

    // Size the grid so that EVERY block is wave-1 resident (deadlock-free by
    // construction). Host-side queries only; nothing here is captured.
    int dev = 0, sms = 0, occ = 0;
    cudaGetDevice(&dev);
    cudaDeviceGetAttribute(&sms, cudaDevAttrMultiProcessorCount, dev);
    cudaOccupancyMaxActiveBlocksPerMultiprocessor(&occ, clahe_fused_kernel,
                                                  256, 0);
    if (sms <= 0) sms = 148;
    if (occ <= 0) occ = 1;
    if (occ > 6)  occ = 6;
    int NB = sms * occ;
    if (NB < 2) NB = 2;

    clahe_init_kernel<<<1, 128>>>();
    clahe_fused_kernel<<<NB, 256>>>(x, out);
}